// round 1
// baseline (speedup 1.0000x reference)
#include <cuda_runtime.h>
#include <cstdint>

#define Bsz 8
#define Nn 1024
#define Ee 256
#define Dm 64
#define Hh 4
#define DH 16

// ---------------- device scratch (no allocations allowed) ----------------
__device__ float d_qk[2][Bsz][Hh][Nn][DH];        // q, k                 (4 MB)
__device__ float d_e [4][Bsz][Hh][Ee][DH];        // eq, ek, ceq, cek     (2 MB)
__device__ float d_rdiv[2][Bsz][Nn];              // 1/div per branch
__device__ float d_g [2][2][Bsz][Hh][Nn][DH];     // [branch][q|k]        (16 MB)

// ---------------- K1: emb -> q,k ----------------
__global__ void k_qk(const float* __restrict__ x,
                     const float* __restrict__ W_emb, const float* __restrict__ b_emb,
                     const float* __restrict__ W_q,   const float* __restrict__ b_q,
                     const float* __restrict__ W_k,   const float* __restrict__ b_k) {
    int bn  = blockIdx.x;          // 0..B*N-1
    int tid = threadIdx.x;         // 0..63
    __shared__ float emb[64];
    float x0 = x[bn * 2 + 0];
    float x1 = x[bn * 2 + 1];
    emb[tid] = x0 * W_emb[tid] + x1 * W_emb[64 + tid] + b_emb[tid];
    __syncthreads();
    float q = b_q[tid], k = b_k[tid];
#pragma unroll
    for (int j = 0; j < 64; ++j) {
        float e = emb[j];
        q = fmaf(e, W_q[j * 64 + tid], q);
        k = fmaf(e, W_k[j * 64 + tid], k);
    }
    int b = bn >> 10, n = bn & 1023;
    int h = tid >> 4, c = tid & 15;
    int off = ((b * Hh + h) * Nn + n) * DH + c;
    (&d_qk[0][0][0][0][0])[off] = q;
    (&d_qk[1][0][0][0][0])[off] = k;
}

// ---------------- K2: edge projections (eq, ek, ceq, cek) ----------------
__global__ void k_edge(const float* __restrict__ edge, const float* __restrict__ cedge,
                       const float* __restrict__ W_eq,  const float* __restrict__ b_eq,
                       const float* __restrict__ W_ek,  const float* __restrict__ b_ek,
                       const float* __restrict__ W_ceq, const float* __restrict__ b_ceq,
                       const float* __restrict__ W_cek, const float* __restrict__ b_cek) {
    int i = blockIdx.x * blockDim.x + threadIdx.x;   // 0 .. 4*8192*16-1
    int c = i & 15;
    int r = (i >> 4) & 8191;                         // (b*H + h)*E + e
    int t = i >> 17;                                 // 0..3
    const float* src = (t < 2 ? edge : cedge) + r * 16;
    const float* W; const float* bb;
    if      (t == 0) { W = W_eq;  bb = b_eq;  }
    else if (t == 1) { W = W_ek;  bb = b_ek;  }
    else if (t == 2) { W = W_ceq; bb = b_ceq; }
    else             { W = W_cek; bb = b_cek; }
    float a = bb[c];
#pragma unroll
    for (int j = 0; j < 16; ++j) a = fmaf(src[j], W[j * 16 + c], a);
    (&d_e[0][0][0][0][0])[i] = a;
}

// ---------------- K3: reciprocal of G.sum(axis=E) ----------------
__global__ void k_div(const float* __restrict__ G, const float* __restrict__ CG) {
    int i = blockIdx.x * blockDim.x + threadIdx.x;   // 0 .. 2*B*N-1
    int n = i & 1023;
    int b = (i >> 10) & 7;
    int br = i >> 13;
    const float* Gm = (br ? CG : G) + (size_t)b * Ee * Nn + n;
    float s = 0.f;
#pragma unroll 8
    for (int e = 0; e < Ee; ++e) s += Gm[(size_t)e * Nn];
    (&d_rdiv[0][0][0])[i] = 1.0f / s;
}

// ---------------- K4: gq/gk = q/k + (G^T @ eq/ek) * rdiv ----------------
__global__ void k_gextra(const float* __restrict__ G, const float* __restrict__ CG) {
    int bid = blockIdx.x;                 // 2*8*4*8 = 512 blocks, 128 threads
    int nt = bid & 7;  bid >>= 3;
    int h  = bid & 3;  bid >>= 2;
    int b  = bid & 7;  bid >>= 3;
    int br = bid;
    int n  = nt * 128 + threadIdx.x;
    const float* Gm = (br ? CG : G) + (size_t)b * Ee * Nn + n;
    const float* eq = &d_e[br * 2 + 0][b][h][0][0];
    const float* ek = &d_e[br * 2 + 1][b][h][0][0];
    __shared__ float seq[16][16], sek[16][16];
    float aq[16], ak[16];
#pragma unroll
    for (int c = 0; c < 16; ++c) { aq[c] = 0.f; ak[c] = 0.f; }
    for (int e0 = 0; e0 < Ee; e0 += 16) {
        __syncthreads();
        for (int i = threadIdx.x; i < 256; i += 128) {
            ((float*)seq)[i] = eq[e0 * 16 + i];
            ((float*)sek)[i] = ek[e0 * 16 + i];
        }
        __syncthreads();
#pragma unroll
        for (int ee = 0; ee < 16; ++ee) {
            float g = Gm[(size_t)(e0 + ee) * Nn];
#pragma unroll
            for (int c = 0; c < 16; ++c) {
                aq[c] = fmaf(g, seq[ee][c], aq[c]);
                ak[c] = fmaf(g, sek[ee][c], ak[c]);
            }
        }
    }
    float rd = d_rdiv[br][b][n];
    const float* qrow = &d_qk[0][b][h][n][0];
    const float* krow = &d_qk[1][b][h][n][0];
    float* gqo = &d_g[br][0][b][h][n][0];
    float* gko = &d_g[br][1][b][h][n][0];
#pragma unroll
    for (int c = 0; c < 16; ++c) {
        gqo[c] = qrow[c] + aq[c] * rd;
        gko[c] = krow[c] + ak[c] * rd;
    }
}

// ---------------- K5: scores + softmax (the big one) ----------------
// grid: 512 blocks = (br, b, h, chunk-of-128-rows); block: 256 threads (8 warps)
// gk[1024][16] staged in smem (row stride 20 floats -> conflict-free),
// each warp computes 2 rows at a time; scores kept in registers.
__global__ void __launch_bounds__(256, 2)
k_attn(float* __restrict__ out) {
    int bid = blockIdx.x;
    int chunk = bid & 7;  bid >>= 3;
    int h     = bid & 3;  bid >>= 2;
    int b     = bid & 7;  bid >>= 3;
    int br    = bid;
    const float* gq = &d_g[br][0][b][h][0][0];
    const float* gk = &d_g[br][1][b][h][0][0];
    extern __shared__ float sk[];      // 1024 * 20 floats = 80 KB

    // stage gk -> smem (float4 loads, scalar padded stores)
    for (int i = threadIdx.x; i < 4096; i += 256) {
        int m  = i >> 2;
        int c4 = (i & 3) << 2;
        float4 v = *(const float4*)(gk + m * 16 + c4);
        float* dst = sk + m * 20 + c4;
        dst[0] = v.x; dst[1] = v.y; dst[2] = v.z; dst[3] = v.w;
    }
    __syncthreads();

    int warp = threadIdx.x >> 5, lane = threadIdx.x & 31;
    size_t obase = ((((size_t)br * Bsz + b) * Hh + h) * Nn) * (size_t)Nn;

    for (int it = 0; it < 8; ++it) {
        int n0 = chunk * 128 + it * 16 + warp * 2;   // this warp: rows n0, n0+1
        float q0[16], q1[16];
        const float* g0 = gq + n0 * 16;
#pragma unroll
        for (int c = 0; c < 16; ++c) { q0[c] = g0[c]; q1[c] = g0[16 + c]; }

        float s0[32], s1[32];
        float mx0 = -1e30f, mx1 = -1e30f;
#pragma unroll
        for (int j = 0; j < 32; ++j) {
            const float* kr = sk + (j * 32 + lane) * 20;
            float a0 = 0.f, a1 = 0.f;
#pragma unroll
            for (int c = 0; c < 16; ++c) {
                float kv = kr[c];
                a0 = fmaf(q0[c], kv, a0);
                a1 = fmaf(q1[c], kv, a1);
            }
            a0 *= 0.125f; a1 *= 0.125f;       // 1/sqrt(D_MODEL) = 1/8
            s0[j] = a0; s1[j] = a1;
            mx0 = fmaxf(mx0, a0); mx1 = fmaxf(mx1, a1);
        }
#pragma unroll
        for (int o = 16; o; o >>= 1) {
            mx0 = fmaxf(mx0, __shfl_xor_sync(0xffffffffu, mx0, o));
            mx1 = fmaxf(mx1, __shfl_xor_sync(0xffffffffu, mx1, o));
        }
        float sm0 = 0.f, sm1 = 0.f;
#pragma unroll
        for (int j = 0; j < 32; ++j) {
            s0[j] = __expf(s0[j] - mx0); sm0 += s0[j];
            s1[j] = __expf(s1[j] - mx1); sm1 += s1[j];
        }
#pragma unroll
        for (int o = 16; o; o >>= 1) {
            sm0 += __shfl_xor_sync(0xffffffffu, sm0, o);
            sm1 += __shfl_xor_sync(0xffffffffu, sm1, o);
        }
        float r0 = 1.0f / sm0, r1 = 1.0f / sm1;
        float* o0 = out + obase + (size_t)n0 * Nn + lane;
#pragma unroll
        for (int j = 0; j < 32; ++j) {
            o0[j * 32]        = s0[j] * r0;
            o0[Nn + j * 32]   = s1[j] * r1;
        }
    }
}

// ---------------- launcher ----------------
extern "C" void kernel_launch(void* const* d_in, const int* in_sizes, int n_in,
                              void* d_out, int out_size) {
    const float* x      = (const float*)d_in[0];
    const float* edge   = (const float*)d_in[1];
    const float* cedge  = (const float*)d_in[2];
    const float* G      = (const float*)d_in[3];
    const float* CG     = (const float*)d_in[4];
    const float* W_emb  = (const float*)d_in[5];
    const float* b_emb  = (const float*)d_in[6];
    const float* W_q    = (const float*)d_in[7];
    const float* b_q    = (const float*)d_in[8];
    const float* W_k    = (const float*)d_in[9];
    const float* b_k    = (const float*)d_in[10];
    const float* W_eq   = (const float*)d_in[11];
    const float* b_eq   = (const float*)d_in[12];
    const float* W_ek   = (const float*)d_in[13];
    const float* b_ek   = (const float*)d_in[14];
    const float* W_ceq  = (const float*)d_in[15];
    const float* b_ceq  = (const float*)d_in[16];
    const float* W_cek  = (const float*)d_in[17];
    const float* b_cek  = (const float*)d_in[18];
    float* out = (float*)d_out;

    cudaFuncSetAttribute(k_attn, cudaFuncAttributeMaxDynamicSharedMemorySize, 1024 * 20 * 4);

    k_qk<<<Bsz * Nn, 64>>>(x, W_emb, b_emb, W_q, b_q, W_k, b_k);
    k_edge<<<2048, 256>>>(edge, cedge, W_eq, b_eq, W_ek, b_ek, W_ceq, b_ceq, W_cek, b_cek);
    k_div<<<64, 256>>>(G, CG);
    k_gextra<<<512, 128>>>(G, CG);
    k_attn<<<512, 256, 1024 * 20 * 4>>>(out);
}

// round 2
// speedup vs baseline: 3.9904x; 3.9904x over previous
#include <cuda_runtime.h>
#include <cstdint>

#define Bsz 8
#define Nn 1024
#define Ee 256
#define Dm 64
#define Hh 4
#define DH 16

// ---------------- device scratch ----------------
__device__ float d_qk[2][Bsz][Hh][Nn][DH];        // q, k
__device__ float d_e [4][Bsz][Hh][Ee][DH];        // eq, ek, ceq, cek
__device__ float d_g [2][2][Bsz][Hh][Nn][DH];     // [branch][q|k][b][h][n][c]; gq pre-scaled by 1/8

// ---------------- K1: emb -> q,k ----------------
__global__ void k_qk(const float* __restrict__ x,
                     const float* __restrict__ W_emb, const float* __restrict__ b_emb,
                     const float* __restrict__ W_q,   const float* __restrict__ b_q,
                     const float* __restrict__ W_k,   const float* __restrict__ b_k) {
    int bn  = blockIdx.x;          // 0..B*N-1
    int tid = threadIdx.x;         // 0..63
    __shared__ float emb[64];
    float x0 = x[bn * 2 + 0];
    float x1 = x[bn * 2 + 1];
    emb[tid] = x0 * W_emb[tid] + x1 * W_emb[64 + tid] + b_emb[tid];
    __syncthreads();
    float q = b_q[tid], k = b_k[tid];
#pragma unroll
    for (int j = 0; j < 64; ++j) {
        float e = emb[j];
        q = fmaf(e, W_q[j * 64 + tid], q);
        k = fmaf(e, W_k[j * 64 + tid], k);
    }
    int b = bn >> 10, n = bn & 1023;
    int h = tid >> 4, c = tid & 15;
    int off = ((b * Hh + h) * Nn + n) * DH + c;
    (&d_qk[0][0][0][0][0])[off] = q;
    (&d_qk[1][0][0][0][0])[off] = k;
}

// ---------------- K2: edge projections ----------------
__global__ void k_edge(const float* __restrict__ edge, const float* __restrict__ cedge,
                       const float* __restrict__ W_eq,  const float* __restrict__ b_eq,
                       const float* __restrict__ W_ek,  const float* __restrict__ b_ek,
                       const float* __restrict__ W_ceq, const float* __restrict__ b_ceq,
                       const float* __restrict__ W_cek, const float* __restrict__ b_cek) {
    int i = blockIdx.x * blockDim.x + threadIdx.x;   // 0 .. 4*8192*16-1
    int c = i & 15;
    int r = (i >> 4) & 8191;
    int t = i >> 17;
    const float* src = (t < 2 ? edge : cedge) + r * 16;
    const float* W; const float* bb;
    if      (t == 0) { W = W_eq;  bb = b_eq;  }
    else if (t == 1) { W = W_ek;  bb = b_ek;  }
    else if (t == 2) { W = W_ceq; bb = b_ceq; }
    else             { W = W_cek; bb = b_cek; }
    float a = bb[c];
#pragma unroll
    for (int j = 0; j < 16; ++j) a = fmaf(src[j], W[j * 16 + c], a);
    (&d_e[0][0][0][0][0])[i] = a;
}

// ---------------- K3: gq/gk for ALL 4 heads + div, one pass over G ----------------
// grid: 2br * 8b * 16ntile = 256 blocks; 1024 threads = 64 n x 16 c
__global__ void __launch_bounds__(1024, 2)
k_gextra(const float* __restrict__ G, const float* __restrict__ CG) {
    int bid = blockIdx.x;
    int nt = bid & 15;  bid >>= 4;
    int b  = bid & 7;   bid >>= 3;
    int br = bid;
    int tid = threadIdx.x;
    int nl = tid >> 4;          // 0..63
    int c  = tid & 15;
    int nbase = nt * 64;

    const float* Gm  = (br ? CG : G) + (size_t)b * Ee * Nn;
    const float* eqb = &d_e[br * 2 + 0][b][0][0][0];   // [h][e][c]
    const float* ekb = &d_e[br * 2 + 1][b][0][0][0];

    __shared__ float sg[16][64];
    __shared__ float seq[4][16][16];
    __shared__ float sek[4][16][16];

    float aq[4] = {0.f, 0.f, 0.f, 0.f};
    float ak[4] = {0.f, 0.f, 0.f, 0.f};
    float gsum = 0.f;

    for (int e0 = 0; e0 < Ee; e0 += 16) {
        __syncthreads();
        {
            int se = tid >> 6, sn = tid & 63;
            sg[se][sn] = Gm[(size_t)(e0 + se) * Nn + nbase + sn];
            int sh = tid >> 8, see = (tid >> 4) & 15, sc = tid & 15;
            seq[sh][see][sc] = eqb[(sh * Ee + e0 + see) * DH + sc];
            sek[sh][see][sc] = ekb[(sh * Ee + e0 + see) * DH + sc];
        }
        __syncthreads();
#pragma unroll
        for (int ee = 0; ee < 16; ++ee) {
            float g = sg[ee][nl];
            gsum += g;
#pragma unroll
            for (int h = 0; h < 4; ++h) {
                aq[h] = fmaf(g, seq[h][ee][c], aq[h]);
                ak[h] = fmaf(g, sek[h][ee][c], ak[h]);
            }
        }
    }
    float rd = 1.0f / gsum;
    int n = nbase + nl;
#pragma unroll
    for (int h = 0; h < 4; ++h) {
        float q = d_qk[0][b][h][n][c];
        float k = d_qk[1][b][h][n][c];
        // fold score scale 1/sqrt(64) = 1/8 into gq
        d_g[br][0][b][h][n][c] = (q + aq[h] * rd) * 0.125f;
        d_g[br][1][b][h][n][c] = (k + ak[h] * rd);
    }
}

// ---------------- K4: scores + softmax ----------------
// grid: 2br*8b*4h*16chunk(64 rows) = 1024 blocks; 256 threads (8 warps).
// Warp w: half = w&1 (k-range half of 512), rowpair = w>>1. Per iteration a warp
// computes 2 rows x 512 cols -> s0[16],s1[16] regs; cross-half softmax via smem.
__global__ void __launch_bounds__(256, 2)
k_attn(float* __restrict__ out) {
    int bid = blockIdx.x;
    int chunk = bid & 15;  bid >>= 4;
    int h     = bid & 3;   bid >>= 2;
    int b     = bid & 7;   bid >>= 3;
    int br    = bid;
    const float* gq = &d_g[br][0][b][h][0][0];
    const float* gk = &d_g[br][1][b][h][0][0];
    extern __shared__ float sk[];            // 1024 * 20 floats = 80 KB
    __shared__ float redm[2][4][2];          // [half][rowpair][row]
    __shared__ float reds[2][4][2];

    // stage gk -> smem, row stride 20 (LDS.128 conflict-free)
    for (int i = threadIdx.x; i < 4096; i += 256) {
        int m  = i >> 2;
        int c4 = (i & 3) << 2;
        float4 v = *(const float4*)(gk + m * 16 + c4);
        float* dst = sk + m * 20 + c4;
        dst[0] = v.x; dst[1] = v.y; dst[2] = v.z; dst[3] = v.w;
    }
    __syncthreads();

    int warp = threadIdx.x >> 5, lane = threadIdx.x & 31;
    int half = warp & 1, rp = warp >> 1;     // rp: 0..3
    size_t obase = ((((size_t)br * Bsz + b) * Hh + h) * Nn) * (size_t)Nn;

    for (int it = 0; it < 8; ++it) {
        int r0 = chunk * 64 + it * 8 + rp * 2;   // rows r0, r0+1
        float q0[16], q1[16];
        const float* g0 = gq + r0 * 16;
#pragma unroll
        for (int c = 0; c < 16; ++c) { q0[c] = g0[c]; q1[c] = g0[16 + c]; }

        float s0[16], s1[16];
        float mx0 = -1e30f, mx1 = -1e30f;
#pragma unroll
        for (int j = 0; j < 16; ++j) {
            const float* kr = sk + (half * 512 + j * 32 + lane) * 20;
            float a0 = 0.f, a1 = 0.f;
#pragma unroll
            for (int c = 0; c < 16; ++c) {
                float kv = kr[c];
                a0 = fmaf(q0[c], kv, a0);
                a1 = fmaf(q1[c], kv, a1);
            }
            s0[j] = a0; s1[j] = a1;
            mx0 = fmaxf(mx0, a0); mx1 = fmaxf(mx1, a1);
        }
#pragma unroll
        for (int o = 16; o; o >>= 1) {
            mx0 = fmaxf(mx0, __shfl_xor_sync(0xffffffffu, mx0, o));
            mx1 = fmaxf(mx1, __shfl_xor_sync(0xffffffffu, mx1, o));
        }
        if (lane == 0) { redm[half][rp][0] = mx0; redm[half][rp][1] = mx1; }
        __syncthreads();
        mx0 = fmaxf(redm[0][rp][0], redm[1][rp][0]);
        mx1 = fmaxf(redm[0][rp][1], redm[1][rp][1]);

        float sm0 = 0.f, sm1 = 0.f;
#pragma unroll
        for (int j = 0; j < 16; ++j) {
            s0[j] = __expf(s0[j] - mx0); sm0 += s0[j];
            s1[j] = __expf(s1[j] - mx1); sm1 += s1[j];
        }
#pragma unroll
        for (int o = 16; o; o >>= 1) {
            sm0 += __shfl_xor_sync(0xffffffffu, sm0, o);
            sm1 += __shfl_xor_sync(0xffffffffu, sm1, o);
        }
        if (lane == 0) { reds[half][rp][0] = sm0; reds[half][rp][1] = sm1; }
        __syncthreads();
        float r0s = 1.0f / (reds[0][rp][0] + reds[1][rp][0]);
        float r1s = 1.0f / (reds[0][rp][1] + reds[1][rp][1]);

        float* o0 = out + obase + (size_t)r0 * Nn + half * 512 + lane;
#pragma unroll
        for (int j = 0; j < 16; ++j) {
            o0[j * 32]      = s0[j] * r0s;
            o0[Nn + j * 32] = s1[j] * r1s;
        }
    }
}

// ---------------- launcher ----------------
extern "C" void kernel_launch(void* const* d_in, const int* in_sizes, int n_in,
                              void* d_out, int out_size) {
    const float* x      = (const float*)d_in[0];
    const float* edge   = (const float*)d_in[1];
    const float* cedge  = (const float*)d_in[2];
    const float* G      = (const float*)d_in[3];
    const float* CG     = (const float*)d_in[4];
    const float* W_emb  = (const float*)d_in[5];
    const float* b_emb  = (const float*)d_in[6];
    const float* W_q    = (const float*)d_in[7];
    const float* b_q    = (const float*)d_in[8];
    const float* W_k    = (const float*)d_in[9];
    const float* b_k    = (const float*)d_in[10];
    const float* W_eq   = (const float*)d_in[11];
    const float* b_eq   = (const float*)d_in[12];
    const float* W_ek   = (const float*)d_in[13];
    const float* b_ek   = (const float*)d_in[14];
    const float* W_ceq  = (const float*)d_in[15];
    const float* b_ceq  = (const float*)d_in[16];
    const float* W_cek  = (const float*)d_in[17];
    const float* b_cek  = (const float*)d_in[18];
    float* out = (float*)d_out;

    cudaFuncSetAttribute(k_attn, cudaFuncAttributeMaxDynamicSharedMemorySize, 1024 * 20 * 4);

    k_qk<<<Bsz * Nn, 64>>>(x, W_emb, b_emb, W_q, b_q, W_k, b_k);
    k_edge<<<2048, 256>>>(edge, cedge, W_eq, b_eq, W_ek, b_ek, W_ceq, b_ceq, W_cek, b_cek);
    k_gextra<<<256, 1024>>>(G, CG);
    k_attn<<<1024, 256, 1024 * 20 * 4>>>(out);
}